// round 2
// baseline (speedup 1.0000x reference)
#include <cuda_runtime.h>
#include <cuda_bf16.h>
#include <cstdint>

// Problem constants (shapes fixed by dataset)
#define BB   16      // batch
#define CC   32      // channels in added; original has CC+1
#define HH   256     // grid H = W
#define TT   20      // boxes per batch
#define CELLS (HH*HH)
#define VOX  0.8f
#define INVVOX 1.25f

#define GX 64        // blocks along cell dim
#define NBLOCKS (GX * BB)

// Cross-block scratch (no cudaMalloc allowed). Zero-initialized at load;
// the last block resets them after use so every graph replay starts clean.
__device__ unsigned int g_inter[BB];
__device__ unsigned int g_union[BB];
__device__ unsigned int g_ticket;

__global__ void __launch_bounds__(256, 8)
k_fused(const float* __restrict__ added,
        const float* __restrict__ orig,
        const float* __restrict__ boxes,
        float* __restrict__ out) {
    const int b = blockIdx.y;

    // ---- per-batch box preload into shared --------------------------------
    __shared__ float s_cx[TT], s_cy[TT], s_c[TT], s_s[TT], s_hx[TT], s_hy[TT];
    __shared__ int   s_i0[TT], s_i1[TT], s_j0[TT], s_j1[TT];
    if (threadIdx.x < TT) {
        const float* bx = boxes + ((size_t)b * TT + threadIdx.x) * 7;
        const float cx = bx[0], cy = bx[1], cz = bx[2];
        const float dx = bx[3], dy = bx[4], dz = bx[5], yaw = bx[6];
        const float c  = cosf(yaw), s = sinf(yaw);
        const float hx = 0.5f * dx, hy = 0.5f * dy;
        // rotated-box AABB (meters) with +1 cell safety margin
        const float ax = hx * fabsf(c) + hy * fabsf(s);
        const float ay = hx * fabsf(s) + hy * fabsf(c);
        int i0 = max(0,      (int)floorf((cx - ax) * INVVOX) - 1);
        int i1 = min(HH - 1, (int)ceilf ((cx + ax) * INVVOX) + 1);
        int j0 = max(0,      (int)floorf((cy - ay) * INVVOX) - 1);
        int j1 = min(HH - 1, (int)ceilf ((cy + ay) * INVVOX) + 1);
        // z test is constant per box: |0.8 - cz| <= dz/2 (reference uses <=)
        if (fabsf(VOX - cz) > 0.5f * dz) { i0 = 1; i1 = 0; }  // empty AABB
        s_cx[threadIdx.x] = cx;  s_cy[threadIdx.x] = cy;
        s_c [threadIdx.x] = c;   s_s [threadIdx.x] = s;
        s_hx[threadIdx.x] = hx;  s_hy[threadIdx.x] = hy;
        s_i0[threadIdx.x] = i0;  s_i1[threadIdx.x] = i1;
        s_j0[threadIdx.x] = j0;  s_j1[threadIdx.x] = j1;
    }
    __syncthreads();

    // ---- in-box test for this thread's 4 consecutive cells ----------------
    const int tid4  = blockIdx.x * blockDim.x + threadIdx.x;   // 0..16383
    const int cell0 = tid4 * 4;
    const int i     = cell0 >> 8;          // row
    const int jbase = cell0 & 255;         // first column of the 4-cell span
    const float px  = (float)i * VOX;

    unsigned int mword = 0u;               // 4 mask bits
    #pragma unroll 4
    for (int t = 0; t < TT; t++) {
        if (i < s_i0[t] || i > s_i1[t]) continue;              // row reject
        if (jbase + 3 < s_j0[t] || jbase > s_j1[t]) continue;  // col reject
        const float c  = s_c[t],  s  = s_s[t];
        const float hx = s_hx[t], hy = s_hy[t];
        const float dxp = px - s_cx[t];
        const float cy  = s_cy[t];
        #pragma unroll
        for (int k = 0; k < 4; k++) {
            const float py = (float)(jbase + k) * VOX - cy;
            const float rx = fmaf(py, s,  dxp * c);
            const float ry = fmaf(py, c, -dxp * s);
            if (fabsf(rx) < hx && fabsf(ry) < hy) mword |= (1u << k);
        }
        if (mword == 0xFu) break;
    }

    // ---- masked channel reduce + IoU bits ---------------------------------
    unsigned int inter = 0u, uni = 0u;
    if (mword != 0u) {
        const float* ap = added + ((size_t)b * CC) * CELLS + cell0;
        const float* op = orig  + ((size_t)b * (CC + 1) + 1) * CELLS + cell0;
        float4 sp = make_float4(0.f, 0.f, 0.f, 0.f);
        float4 so = make_float4(0.f, 0.f, 0.f, 0.f);
        #pragma unroll 8
        for (int ch = 0; ch < CC; ch++) {
            const float4 va = *(const float4*)(ap + (size_t)ch * CELLS);
            const float4 vo = *(const float4*)(op + (size_t)ch * CELLS);
            sp.x += va.x; sp.y += va.y; sp.z += va.z; sp.w += va.w;
            so.x += vo.x; so.y += vo.y; so.z += vo.z; so.w += vo.w;
        }
        const float spv[4] = {sp.x, sp.y, sp.z, sp.w};
        const float sov[4] = {so.x, so.y, so.z, so.w};
        #pragma unroll
        for (int k = 0; k < 4; k++) {
            const bool m = (mword >> k) & 1u;
            const bool p = m && (spv[k] != 0.0f);
            const bool o = m && (sov[k] != 0.0f);
            inter += (unsigned)(p && o);
            uni   += (unsigned)(p || o);
        }
    }

    // ---- block reduce -----------------------------------------------------
    inter = __reduce_add_sync(0xFFFFFFFFu, inter);
    uni   = __reduce_add_sync(0xFFFFFFFFu, uni);

    __shared__ unsigned int s_ri[8], s_ru[8];
    const int lane = threadIdx.x & 31;
    const int wid  = threadIdx.x >> 5;
    if (lane == 0) { s_ri[wid] = inter; s_ru[wid] = uni; }
    __syncthreads();
    if (wid == 0) {
        unsigned int vi = (lane < 8) ? s_ri[lane] : 0u;
        unsigned int vu = (lane < 8) ? s_ru[lane] : 0u;
        vi = __reduce_add_sync(0xFFFFFFFFu, vi);
        vu = __reduce_add_sync(0xFFFFFFFFu, vu);
        if (lane == 0 && (vi | vu)) {
            atomicAdd(&g_inter[b], vi);
            atomicAdd(&g_union[b], vu);
        }
    }

    // ---- last-block finalization (and scratch reset for graph replay) -----
    __shared__ unsigned int s_last;
    if (threadIdx.x == 0) {
        __threadfence();
        s_last = (atomicAdd(&g_ticket, 1u) == (unsigned)(NBLOCKS - 1)) ? 1u : 0u;
    }
    __syncthreads();
    if (s_last && wid == 0) {
        float iou = 0.0f;
        if (lane < BB) {
            const unsigned int vi = g_inter[lane];
            const unsigned int vu = g_union[lane];
            g_inter[lane] = 0u;                 // reset for next replay
            g_union[lane] = 0u;
            iou = (float)vi / fmaxf((float)vu, 1.0f);
        }
        #pragma unroll
        for (int off = 16; off > 0; off >>= 1)
            iou += __shfl_xor_sync(0xFFFFFFFFu, iou, off);
        if (lane == 0) {
            out[0] = (float)TT * iou / (float)BB;
            __threadfence();
            g_ticket = 0u;                      // reset ticket for next replay
        }
    }
}

extern "C" void kernel_launch(void* const* d_in, const int* in_sizes, int n_in,
                              void* d_out, int out_size) {
    const float* added = (const float*)d_in[0];   // (16,32,256,256)
    const float* orig  = (const float*)d_in[1];   // (16,33,256,256)
    const float* boxes = (const float*)d_in[2];   // (16,20,7)
    (void)in_sizes; (void)n_in; (void)out_size;   // tf_ego unused

    k_fused<<<dim3(GX, BB), 256>>>(added, orig, boxes, (float*)d_out);
}

// round 3
// speedup vs baseline: 1.9548x; 1.9548x over previous
#include <cuda_runtime.h>
#include <cuda_bf16.h>
#include <cstdint>

// Problem constants (shapes fixed by dataset)
#define BB   16      // batch
#define CC   32      // channels in added; original has CC+1
#define HH   256     // grid H = W
#define TT   20      // boxes per batch
#define CELLS (HH*HH)
#define VOX  0.8f
#define INVVOX 1.25f

#define BLK  128     // threads per block
#define GX   128     // blocks along cell dim (GX*BLK*4 == CELLS)
#define NBLOCKS (GX * BB)

// Cross-block scratch (no cudaMalloc allowed). Zero-initialized at load;
// the last block resets everything so every graph replay starts clean.
__device__ unsigned int g_inter[BB];
__device__ unsigned int g_union[BB];
__device__ unsigned int g_ticket;

__global__ void __launch_bounds__(BLK)
k_fused(const float* __restrict__ added,
        const float* __restrict__ orig,
        const float* __restrict__ boxes,
        float* __restrict__ out) {
    const int b = blockIdx.y;

    // ---- per-batch box preload into shared --------------------------------
    __shared__ float s_cx[TT], s_cy[TT], s_c[TT], s_s[TT], s_hx[TT], s_hy[TT];
    __shared__ int   s_i0[TT], s_i1[TT], s_j0[TT], s_j1[TT];
    if (threadIdx.x < TT) {
        const float* bx = boxes + ((size_t)b * TT + threadIdx.x) * 7;
        const float cx = bx[0], cy = bx[1], cz = bx[2];
        const float dx = bx[3], dy = bx[4], dz = bx[5], yaw = bx[6];
        const float c  = cosf(yaw), s = sinf(yaw);
        const float hx = 0.5f * dx, hy = 0.5f * dy;
        // rotated-box AABB (meters) with +1 cell safety margin
        const float ax = hx * fabsf(c) + hy * fabsf(s);
        const float ay = hx * fabsf(s) + hy * fabsf(c);
        int i0 = max(0,      (int)floorf((cx - ax) * INVVOX) - 1);
        int i1 = min(HH - 1, (int)ceilf ((cx + ax) * INVVOX) + 1);
        int j0 = max(0,      (int)floorf((cy - ay) * INVVOX) - 1);
        int j1 = min(HH - 1, (int)ceilf ((cy + ay) * INVVOX) + 1);
        // z test constant per box: |0.8 - cz| <= dz/2  (reference uses <=)
        if (fabsf(VOX - cz) > 0.5f * dz) { i0 = 1; i1 = 0; }  // empty AABB
        s_cx[threadIdx.x] = cx;  s_cy[threadIdx.x] = cy;
        s_c [threadIdx.x] = c;   s_s [threadIdx.x] = s;
        s_hx[threadIdx.x] = hx;  s_hy[threadIdx.x] = hy;
        s_i0[threadIdx.x] = i0;  s_i1[threadIdx.x] = i1;
        s_j0[threadIdx.x] = j0;  s_j1[threadIdx.x] = j1;
    }
    __syncthreads();

    // ---- in-box test for this thread's 4 consecutive cells ----------------
    const int tid4  = blockIdx.x * BLK + threadIdx.x;   // 0..16383 (uint4 idx)
    const int cell0 = tid4 * 4;
    const int i     = cell0 >> 8;          // row
    const int jbase = cell0 & 255;         // first column of the 4-cell span
    const float px  = (float)i * VOX;

    unsigned int mword = 0u;               // 4 mask bits
    for (int t = 0; t < TT; t++) {
        if (i < s_i0[t] || i > s_i1[t]) continue;              // row reject
        if (jbase + 3 < s_j0[t] || jbase > s_j1[t]) continue;  // col reject
        const float c  = s_c[t],  s  = s_s[t];
        const float hx = s_hx[t], hy = s_hy[t];
        const float dxp = px - s_cx[t];
        const float cy  = s_cy[t];
        #pragma unroll
        for (int k = 0; k < 4; k++) {
            const float py = (float)(jbase + k) * VOX - cy;
            const float rx = fmaf(py, s,  dxp * c);
            const float ry = fmaf(py, c, -dxp * s);
            if (fabsf(rx) < hx && fabsf(ry) < hy) mword |= (1u << k);
        }
        if (mword == 0xFu) break;
    }

    // ---- masked channel reduce (integer OR; inputs are non-negative) ------
    unsigned int inter = 0u, uni = 0u;
    if (mword != 0u) {
        // uint4 index of this group within a channel plane = tid4
        const uint4* ap = (const uint4*)(added) + ((size_t)b * CC)           * (CELLS/4) + tid4;
        const uint4* op = (const uint4*)(orig)  + ((size_t)b * (CC+1) + 1)   * (CELLS/4) + tid4;
        uint4 aa = make_uint4(0u,0u,0u,0u);
        uint4 ao = make_uint4(0u,0u,0u,0u);
        #pragma unroll
        for (int cb = 0; cb < 4; cb++) {
            uint4 va[8], vo[8];
            #pragma unroll
            for (int u = 0; u < 8; u++)
                va[u] = ap[(size_t)(cb * 8 + u) * (CELLS/4)];
            #pragma unroll
            for (int u = 0; u < 8; u++)
                vo[u] = op[(size_t)(cb * 8 + u) * (CELLS/4)];
            #pragma unroll
            for (int u = 0; u < 8; u++) {
                aa.x |= va[u].x; aa.y |= va[u].y; aa.z |= va[u].z; aa.w |= va[u].w;
                ao.x |= vo[u].x; ao.y |= vo[u].y; ao.z |= vo[u].z; ao.w |= vo[u].w;
            }
        }
        const unsigned int av[4] = {aa.x, aa.y, aa.z, aa.w};
        const unsigned int ov[4] = {ao.x, ao.y, ao.z, ao.w};
        #pragma unroll
        for (int k = 0; k < 4; k++) {
            const bool m = (mword >> k) & 1u;
            const bool p = m && (av[k] != 0u);   // any channel nonzero
            const bool o = m && (ov[k] != 0u);
            inter += (unsigned)(p && o);
            uni   += (unsigned)(p || o);
        }
    }

    // ---- block reduce (4 warps) -------------------------------------------
    inter = __reduce_add_sync(0xFFFFFFFFu, inter);
    uni   = __reduce_add_sync(0xFFFFFFFFu, uni);

    __shared__ unsigned int s_ri[4], s_ru[4];
    const int lane = threadIdx.x & 31;
    const int wid  = threadIdx.x >> 5;
    if (lane == 0) { s_ri[wid] = inter; s_ru[wid] = uni; }
    __syncthreads();
    if (wid == 0 && lane == 0) {
        const unsigned int vi = s_ri[0] + s_ri[1] + s_ri[2] + s_ri[3];
        const unsigned int vu = s_ru[0] + s_ru[1] + s_ru[2] + s_ru[3];
        if (vi | vu) {
            atomicAdd(&g_inter[b], vi);
            atomicAdd(&g_union[b], vu);
        }
    }

    // ---- last-block finalization (+ scratch reset for graph replay) -------
    __shared__ unsigned int s_last;
    if (threadIdx.x == 0) {
        __threadfence();
        s_last = (atomicAdd(&g_ticket, 1u) == (unsigned)(NBLOCKS - 1)) ? 1u : 0u;
    }
    __syncthreads();
    if (s_last && wid == 0) {
        float iou = 0.0f;
        if (lane < BB) {
            const unsigned int vi = g_inter[lane];
            const unsigned int vu = g_union[lane];
            g_inter[lane] = 0u;                  // reset for next replay
            g_union[lane] = 0u;
            iou = (float)vi / fmaxf((float)vu, 1.0f);
        }
        #pragma unroll
        for (int off = 16; off > 0; off >>= 1)
            iou += __shfl_xor_sync(0xFFFFFFFFu, iou, off);
        if (lane == 0) {
            out[0] = (float)TT * iou / (float)BB;
            __threadfence();
            g_ticket = 0u;                       // reset ticket for next replay
        }
    }
}

extern "C" void kernel_launch(void* const* d_in, const int* in_sizes, int n_in,
                              void* d_out, int out_size) {
    const float* added = (const float*)d_in[0];   // (16,32,256,256)
    const float* orig  = (const float*)d_in[1];   // (16,33,256,256)
    const float* boxes = (const float*)d_in[2];   // (16,20,7)
    (void)in_sizes; (void)n_in; (void)out_size;   // tf_ego unused

    k_fused<<<dim3(GX, BB), BLK>>>(added, orig, boxes, (float*)d_out);
}